// round 3
// baseline (speedup 1.0000x reference)
#include <cuda_runtime.h>

#define NB 32
#define NL 8192
#define NC 32
#define NF 32
#define NK 5
#define TL 8                 // positions per CTA (= warps per CTA)
#define ROWS (TL + 3)        // halo: 2 before, 1 after
#define PAD 34               // b-dim padding: 8B-aligned pairs, 2-way max bank conflict

// Inter-layer scratch for h = leaky(bn(lc1(x)))  (static device array: no runtime alloc)
__device__ float g_h[(size_t)NB * NL * NC];

__device__ __forceinline__ unsigned long long dup2(float w) {
    unsigned long long r;
    unsigned int u = __float_as_uint(w);
    asm("mov.b64 %0, {%1, %1};" : "=l"(r) : "r"(u));
    return r;
}
__device__ __forceinline__ void fma2(unsigned long long& d, unsigned long long a, unsigned long long b) {
    asm("fma.rn.f32x2 %0, %1, %2, %0;" : "+l"(d) : "l"(a), "l"(b));
}
__device__ __forceinline__ float2 unpk(unsigned long long v) {
    float2 f;
    asm("mov.b64 {%0, %1}, %2;" : "=f"(f.x), "=f"(f.y) : "l"(v));
    return f;
}
__device__ __forceinline__ float lky(float v) { return v >= 0.f ? v : 0.3f * v; }

template <bool SECOND>
__global__ void __launch_bounds__(256)
lc_kernel(const float* __restrict__ in,      // layer input (x for L1; ignored for L2 -> g_h)
          const float* __restrict__ wts,     // [K, L, C, F]
          const float* __restrict__ bias,    // [L, F]
          const float* __restrict__ gamma,
          const float* __restrict__ beta,
          const float* __restrict__ mean,
          const float* __restrict__ var,
          const float* __restrict__ residx,  // original x (L2 only)
          float* __restrict__ out)           // g_h for L1 (ignored), d_out for L2
{
    __shared__ float sx[ROWS * NC * PAD];

    const int tid = threadIdx.x;
    const int l0 = blockIdx.x * TL;
    const float* src = SECOND ? (const float*)g_h : in;

    // Stage input tile, transposed to [lp][c][b] so batch is innermost (paired LDS.64)
    for (int idx = tid; idx < NB * ROWS * NC; idx += 256) {
        int b   = idx / (ROWS * NC);
        int rem = idx - b * (ROWS * NC);
        int lp  = rem >> 5;
        int c   = rem & 31;
        int gl  = (l0 + lp - 2) & (NL - 1);     // circular roll, L power of 2
        sx[(lp * NC + c) * PAD + b] = src[((size_t)b * NL + gl) * NC + c];
    }
    __syncthreads();

    const int warp = tid >> 5;
    const int lane = tid & 31;
    const int l  = l0 + warp;                   // one warp owns one position
    const int f0 = (lane & 7) << 2;             // 4 filters per thread
    const int b0 = (lane >> 3) << 3;            // 8 batches per thread (4 f32x2 pairs)

    unsigned long long acc[4][4];               // [batch-pair][filter]
    #pragma unroll
    for (int i = 0; i < 4; ++i)
        #pragma unroll
        for (int j = 0; j < 4; ++j) acc[i][j] = 0ull;

    // steps = {0,0,1,-1,2}; xs[l] = x[l-step]; local row offset = 2 - step
    const int OFFv[5] = {2, 2, 1, 3, 0};

    #pragma unroll
    for (int i = 0; i < NK; ++i) {
        const float* wp = wts + (((size_t)i * NL + l) * NC) * NF + f0;
        const float* xb = sx + (warp + OFFv[i]) * (NC * PAD) + b0;
        #pragma unroll 8
        for (int c = 0; c < NC; ++c) {
            float4 w4 = __ldcs(reinterpret_cast<const float4*>(wp + c * NF));
            unsigned long long wd0 = dup2(w4.x), wd1 = dup2(w4.y),
                               wd2 = dup2(w4.z), wd3 = dup2(w4.w);
            const float* xr = xb + c * PAD;
            unsigned long long x0 = *reinterpret_cast<const unsigned long long*>(xr);
            unsigned long long x1 = *reinterpret_cast<const unsigned long long*>(xr + 2);
            unsigned long long x2 = *reinterpret_cast<const unsigned long long*>(xr + 4);
            unsigned long long x3 = *reinterpret_cast<const unsigned long long*>(xr + 6);
            fma2(acc[0][0], x0, wd0); fma2(acc[0][1], x0, wd1);
            fma2(acc[0][2], x0, wd2); fma2(acc[0][3], x0, wd3);
            fma2(acc[1][0], x1, wd0); fma2(acc[1][1], x1, wd1);
            fma2(acc[1][2], x1, wd2); fma2(acc[1][3], x1, wd3);
            fma2(acc[2][0], x2, wd0); fma2(acc[2][1], x2, wd1);
            fma2(acc[2][2], x2, wd2); fma2(acc[2][3], x2, wd3);
            fma2(acc[3][0], x3, wd0); fma2(acc[3][1], x3, wd1);
            fma2(acc[3][2], x3, wd2); fma2(acc[3][3], x3, wd3);
        }
    }

    // Epilogue: fold BN + the reference's double-added bias into scale/shift
    float4 ga = *reinterpret_cast<const float4*>(gamma + f0);
    float4 bt = *reinterpret_cast<const float4*>(beta + f0);
    float4 mn = *reinterpret_cast<const float4*>(mean + f0);
    float4 vr = *reinterpret_cast<const float4*>(var + f0);
    float4 bi = *reinterpret_cast<const float4*>(bias + (size_t)l * NF + f0);

    float scv[4], shv[4];
    scv[0] = ga.x * rsqrtf(vr.x + 1e-3f); shv[0] = bt.x + (2.f * bi.x - mn.x) * scv[0];
    scv[1] = ga.y * rsqrtf(vr.y + 1e-3f); shv[1] = bt.y + (2.f * bi.y - mn.y) * scv[1];
    scv[2] = ga.z * rsqrtf(vr.z + 1e-3f); shv[2] = bt.z + (2.f * bi.z - mn.z) * scv[2];
    scv[3] = ga.w * rsqrtf(vr.w + 1e-3f); shv[3] = bt.w + (2.f * bi.w - mn.w) * scv[3];

    float* dstbase = SECOND ? out : (float*)g_h;

    #pragma unroll
    for (int bp = 0; bp < 4; ++bp) {
        float2 v[4];
        #pragma unroll
        for (int ff = 0; ff < 4; ++ff) v[ff] = unpk(acc[bp][ff]);

        const int bl = b0 + 2 * bp;
        float o0[4], o1[4];
        #pragma unroll
        for (int ff = 0; ff < 4; ++ff) {
            o0[ff] = v[ff].x * scv[ff] + shv[ff];
            o1[ff] = v[ff].y * scv[ff] + shv[ff];
        }
        if (SECOND) {
            float4 r0 = *reinterpret_cast<const float4*>(residx + ((size_t)bl * NL + l) * NC + f0);
            float4 r1 = *reinterpret_cast<const float4*>(residx + ((size_t)(bl + 1) * NL + l) * NC + f0);
            o0[0] += r0.x; o0[1] += r0.y; o0[2] += r0.z; o0[3] += r0.w;
            o1[0] += r1.x; o1[1] += r1.y; o1[2] += r1.z; o1[3] += r1.w;
        }
        #pragma unroll
        for (int ff = 0; ff < 4; ++ff) { o0[ff] = lky(o0[ff]); o1[ff] = lky(o1[ff]); }

        float* d0 = dstbase + ((size_t)bl * NL + l) * NC + f0;
        float* d1 = dstbase + ((size_t)(bl + 1) * NL + l) * NC + f0;
        *reinterpret_cast<float4*>(d0) = make_float4(o0[0], o0[1], o0[2], o0[3]);
        *reinterpret_cast<float4*>(d1) = make_float4(o1[0], o1[1], o1[2], o1[3]);
    }
}

extern "C" void kernel_launch(void* const* d_in, const int* in_sizes, int n_in,
                              void* d_out, int out_size) {
    (void)in_sizes; (void)n_in; (void)out_size;
    const float* x   = (const float*)d_in[0];
    const float* k1  = (const float*)d_in[1];
    const float* b1  = (const float*)d_in[2];
    const float* g1  = (const float*)d_in[3];
    const float* be1 = (const float*)d_in[4];
    const float* m1  = (const float*)d_in[5];
    const float* v1  = (const float*)d_in[6];
    const float* k2  = (const float*)d_in[7];
    const float* b2  = (const float*)d_in[8];
    const float* g2  = (const float*)d_in[9];
    const float* be2 = (const float*)d_in[10];
    const float* m2  = (const float*)d_in[11];
    const float* v2  = (const float*)d_in[12];
    float* out = (float*)d_out;

    dim3 grid(NL / TL);
    lc_kernel<false><<<grid, 256>>>(x, k1, b1, g1, be1, m1, v1, nullptr, nullptr);
    lc_kernel<true ><<<grid, 256>>>(nullptr, k2, b2, g2, be2, m2, v2, x, out);
}